// round 6
// baseline (speedup 1.0000x reference)
#include <cuda_runtime.h>
#include <cuda_fp16.h>
#include <cstdint>

// Problem constants
#define BB 16
#define SS 2048
#define DD 1024
#define HH 16
#define DK 64
#define CLIPC 8
#define NCC 256
#define MROWS (BB * SS)  // 32768

// ---------------------------------------------------------------------------
// Scratch (static __device__ arrays; no allocation allowed)
// ---------------------------------------------------------------------------
__device__ float g_qs[MROWS * DD];
__device__ float g_ks[MROWS * DD];
__device__ float g_vs[MROWS * DD];
__device__ float g_qt[MROWS * DD];
__device__ float g_kt[MROWS * DD];
__device__ float g_vt[MROWS * DD];
__device__ float g_W1[DD * DD];
__device__ float g_W2[DD * DD];
__device__ float g_bc[DD];
__device__ float g_bcp[32][DD];

// fp16 buffers (A operands: hi only; weights: hi+lo)
__device__ __half g_xh[MROWS * DD];
__device__ __half g_csh[MROWS * DD];   // spatial attention out (fp16, direct)
__device__ __half g_cth[MROWS * DD];   // temporal attention out (fp16, direct)
// transposed+split weights: 0..5 = sa_q,sa_k,sa_v,ta_q,ta_k,ta_v; 6=W1; 7=W2
__device__ __half g_wth[8][DD * DD];
__device__ __half g_wtl[8][DD * DD];

// ---------------------------------------------------------------------------
// Packed f32x2 helpers
// ---------------------------------------------------------------------------
__device__ __forceinline__ unsigned long long pk2(float lo, float hi) {
    unsigned long long r;
    asm("mov.b64 %0, {%1, %2};" : "=l"(r) : "f"(lo), "f"(hi));
    return r;
}
__device__ __forceinline__ void fma2(unsigned long long& d, unsigned long long a,
                                     unsigned long long b) {
    asm("fma.rn.f32x2 %0, %1, %2, %0;" : "+l"(d) : "l"(a), "l"(b));
}
__device__ __forceinline__ void mul2(unsigned long long& d, unsigned long long a) {
    asm("mul.rn.f32x2 %0, %0, %1;" : "+l"(d) : "l"(a));
}
__device__ __forceinline__ float2 upk(unsigned long long v) {
    float2 f;
    asm("mov.b64 {%0, %1}, %2;" : "=f"(f.x), "=f"(f.y) : "l"(v));
    return f;
}

// ---------------------------------------------------------------------------
// mma.sync helpers (base PTX ISA — compiles at .target sm_103)
// ---------------------------------------------------------------------------
__device__ __forceinline__ uint32_t smem_u32(const void* p) {
    uint32_t a;
    asm("{ .reg .u64 t; cvta.to.shared.u64 t, %1; cvt.u32.u64 %0, t; }"
        : "=r"(a) : "l"(p));
    return a;
}
__device__ __forceinline__ void ldsm4(uint32_t* r, uint32_t addr) {
    asm volatile(
        "ldmatrix.sync.aligned.m8n8.x4.shared.b16 {%0,%1,%2,%3}, [%4];"
        : "=r"(r[0]), "=r"(r[1]), "=r"(r[2]), "=r"(r[3]) : "r"(addr));
}
__device__ __forceinline__ void mma16816(float* d, const uint32_t* a,
                                         const uint32_t* b) {
    asm volatile(
        "mma.sync.aligned.m16n8k16.row.col.f32.f16.f16.f32 "
        "{%0,%1,%2,%3}, {%4,%5,%6,%7}, {%8,%9}, {%0,%1,%2,%3};"
        : "+f"(d[0]), "+f"(d[1]), "+f"(d[2]), "+f"(d[3])
        : "r"(a[0]), "r"(a[1]), "r"(a[2]), "r"(a[3]), "r"(b[0]), "r"(b[1]));
}
#define CPASYNC16(dst, src) \
    asm volatile("cp.async.cg.shared.global [%0], [%1], 16;" :: "r"(dst), "l"(src))
#define CPCOMMIT() asm volatile("cp.async.commit_group;" ::: "memory")
#define CPWAIT2() asm volatile("cp.async.wait_group 2;" ::: "memory")

// smem geometry: row pitch 80B (40 fp16). 80 = 5*16, so the 8 rows of any
// ldmatrix 8x8 (stride 80B) hit 8 distinct 16B bank groups -> conflict-free.
#define PITCHB 80
#define TILEB (128 * PITCHB)     // 10240 bytes per operand tile
#define STAGEB (3 * TILEB)       // Ah, Bh, Bl
#define NSTAGE 4
#define SMEM_DYN (NSTAGE * STAGEB)  // 122880 bytes

// ---------------------------------------------------------------------------
// fp16 2-pass GEMM core: C = Ah*Bh^T + Ah*Bl^T + bias
//   (== Ah*(Wh+Wl)^T; dropped term lo(A)*W ~ 2^-12 relative)
// A [M,1024] fp16 row-major, Bt [N=1024,K=1024] fp16 [N,K] (pre-transposed).
// CTA tile 128x128, BK=32, 256 thr = 8 warps (2 M x 4 N), warp tile 64x32.
// (2Mx4N: B-fragments redundantly loaded only 2x instead of 4x -> -20% LDS)
// 4-stage cp.async pipeline, ONE __syncthreads per chunk.
// ---------------------------------------------------------------------------
struct GSrc {
    const __half *Ah, *Bh, *Bl;
};

__device__ __forceinline__ void mma_core(
    GSrc s0, GSrc s1, int nchunk,
    const float* __restrict__ bias, float* __restrict__ C, int bm, int bn)
{
    extern __shared__ char sm[];
    const uint32_t sbase = smem_u32(sm);
    const int tid = threadIdx.x, wid = tid >> 5, l = tid & 31;
    const int wm = (wid >> 2) * 64;  // 2 warp-rows (M)
    const int wn = (wid & 3) * 32;   // 4 warp-cols (N)

    // stage copy: 3 tiles x 512 16B-chunks, 2 chunks per thread per tile
    auto issue = [&](int kc) {
        if (kc < nchunk) {
            const GSrc& s = (kc < 32) ? s0 : s1;
            const int kl = kc & 31;
            const uint32_t st = sbase + (kc % NSTAGE) * STAGEB;
            const __half* srcs[3] = {s.Ah, s.Bh, s.Bl};
#pragma unroll
            for (int t3 = 0; t3 < 3; ++t3) {
                const int rb = (t3 == 0) ? bm : bn;
                const uint32_t doff = st + t3 * TILEB;
                const __half* sp = srcs[t3];
#pragma unroll
                for (int j = 0; j < 2; ++j) {
                    int c = tid + j * 256;
                    int row = c >> 2, pos = c & 3;
                    uint32_t dst = doff + row * PITCHB + pos * 16;
                    const void* src = sp + (size_t)(rb + row) * DD + kl * 32 + pos * 8;
                    CPASYNC16(dst, src);
                }
            }
        }
        CPCOMMIT();
    };

    issue(0);
    issue(1);
    issue(2);

    float acc[4][4][4];
#pragma unroll
    for (int mi = 0; mi < 4; ++mi)
#pragma unroll
        for (int ni = 0; ni < 4; ++ni)
#pragma unroll
            for (int f = 0; f < 4; ++f) acc[mi][ni][f] = 0.0f;

    // ldmatrix per-lane addressing (m = l/8 selects the 8x8 matrix)
    const uint32_t m8 = l >> 3;
    const uint32_t laneArow = (m8 & 1) * 8 + (l & 7);
    const uint32_t laneAkb = (m8 >> 1) * 16;
    const uint32_t laneBrow = (m8 >> 1) * 8 + (l & 7);
    const uint32_t laneBkb = (m8 & 1) * 16;

    for (int kc = 0; kc < nchunk; ++kc) {
        CPWAIT2();            // stage kc resident
        __syncthreads();      // all warps done with stage kc-1 as well
        issue(kc + NSTAGE - 1);  // refill slot (kc-1)%4 — freed by the sync
        const uint32_t st = sbase + (kc % NSTAGE) * STAGEB;
#pragma unroll
        for (int ks = 0; ks < 2; ++ks) {
            const uint32_t kbyte = ks * 32;
            uint32_t ah[4][4];
#pragma unroll
            for (int mi = 0; mi < 4; ++mi) {
                uint32_t r = wm + mi * 16 + laneArow;
                ldsm4(ah[mi], st + 0 * TILEB + r * PITCHB + kbyte + laneAkb);
            }
            uint32_t bh[4][2], bl[4][2];
#pragma unroll
            for (int bi = 0; bi < 2; ++bi) {
                uint32_t r = wn + bi * 16 + laneBrow;
                uint32_t q[4];
                ldsm4(q, st + 1 * TILEB + r * PITCHB + kbyte + laneBkb);
                bh[bi * 2][0] = q[0]; bh[bi * 2][1] = q[1];
                bh[bi * 2 + 1][0] = q[2]; bh[bi * 2 + 1][1] = q[3];
                ldsm4(q, st + 2 * TILEB + r * PITCHB + kbyte + laneBkb);
                bl[bi * 2][0] = q[0]; bl[bi * 2][1] = q[1];
                bl[bi * 2 + 1][0] = q[2]; bl[bi * 2 + 1][1] = q[3];
            }
#pragma unroll
            for (int mi = 0; mi < 4; ++mi)
#pragma unroll
                for (int ni = 0; ni < 4; ++ni) {
                    mma16816(acc[mi][ni], ah[mi], bh[ni]);
                    mma16816(acc[mi][ni], ah[mi], bl[ni]);
                }
        }
    }

    // epilogue: acc frag f: rows l/4 (+8 for f>=2), cols (l%4)*2 + (f&1)
#pragma unroll
    for (int mi = 0; mi < 4; ++mi) {
        const int r0 = bm + wm + mi * 16 + (l >> 2);
#pragma unroll
        for (int ni = 0; ni < 4; ++ni) {
            const int c = bn + wn + ni * 8 + (l & 3) * 2;
            const float b0v = bias[c], b1v = bias[c + 1];
            float2 v0, v1;
            v0.x = acc[mi][ni][0] + b0v;
            v0.y = acc[mi][ni][1] + b1v;
            v1.x = acc[mi][ni][2] + b0v;
            v1.y = acc[mi][ni][3] + b1v;
            *(float2*)(C + (size_t)r0 * DD + c) = v0;
            *(float2*)(C + (size_t)(r0 + 8) * DD + c) = v1;
        }
    }
}

// batched QKV: z selects weight/bias/output; A = x (shared)
struct QkvPtrs {
    const __half* Bh[6];
    const __half* Bl[6];
    const float* bias[6];
    float* C[6];
};

__global__ __launch_bounds__(256) void mma_gemm_qkv(
    const __half* __restrict__ Ah, QkvPtrs p)
{
    int z = blockIdx.z;
    GSrc s{Ah, p.Bh[z], p.Bl[z]};
    mma_core(s, s, 32, p.bias[z], p.C[z], blockIdx.y * 128, blockIdx.x * 128);
}

__global__ __launch_bounds__(256) void mma_gemm_dual(
    const __half* A0h, const __half* B0h, const __half* B0l,
    const __half* A1h, const __half* B1h, const __half* B1l,
    const float* bias, float* C)
{
    GSrc s0{A0h, B0h, B0l};
    GSrc s1{A1h, B1h, B1l};
    mma_core(s0, s1, 64, bias, C, blockIdx.y * 128, blockIdx.x * 128);
}

// ---------------------------------------------------------------------------
// fp32 -> fp16 convert (hi only), vectorized
// ---------------------------------------------------------------------------
__global__ __launch_bounds__(256) void cvt_half(
    const float4* __restrict__ X, __half* __restrict__ H)
{
    size_t idx = (size_t)blockIdx.x * 256 + threadIdx.x;
    float4 v = X[idx];
    __half h[4];
    h[0] = __float2half(v.x);
    h[1] = __float2half(v.y);
    h[2] = __float2half(v.z);
    h[3] = __float2half(v.w);
    *(uint2*)(H + idx * 4) = *(uint2*)h;
}

// ---------------------------------------------------------------------------
// Weight transpose + split: W[K=1024, N=1024] fp32 -> Th/Tl [N,K] fp16
// ---------------------------------------------------------------------------
__global__ __launch_bounds__(256) void wt_split(
    const float* __restrict__ W, __half* __restrict__ Th,
    __half* __restrict__ Tl)
{
    __shared__ float t[32][33];
    int tx = threadIdx.x, ty = threadIdx.y;
    int n0 = blockIdx.x * 32, k0 = blockIdx.y * 32;
#pragma unroll
    for (int j = 0; j < 4; ++j) {
        int k = k0 + ty + j * 8;
        t[ty + j * 8][tx] = W[(size_t)k * DD + n0 + tx];
    }
    __syncthreads();
#pragma unroll
    for (int j = 0; j < 4; ++j) {
        int n = n0 + ty + j * 8;
        int k = k0 + tx;
        float v = t[tx][ty + j * 8];
        __half h = __float2half(v);
        __half lo = __float2half(v - __half2float(h));
        Th[(size_t)n * DD + k] = h;
        Tl[(size_t)n * DD + k] = lo;
    }
}

// ---------------------------------------------------------------------------
// Scalar fp32 GEMM (kept for the two small 1024x1024x1024 weight folds)
// ---------------------------------------------------------------------------
__global__ __launch_bounds__(256) void gemm_kernel(
    const float* __restrict__ A, const float* __restrict__ B,
    const float* __restrict__ bias, float* __restrict__ C,
    int M, int N, int K, int lda, int ldb, int ldc, int accumulate)
{
    __shared__ float As[16][128];
    __shared__ float Bs[16][128];
    const int tid = threadIdx.x;
    const int bm = blockIdx.y * 128;
    const int bn = blockIdx.x * 128;
    const int tm = (tid >> 4) << 3;
    const int tn = (tid & 15) << 3;

    unsigned long long acc2[8][4];
#pragma unroll
    for (int i = 0; i < 8; ++i)
#pragma unroll
        for (int j = 0; j < 4; ++j) acc2[i][j] = 0ull;

    const int nk = K >> 4;
    float4 aR[2], bR[2];
    auto loadTile = [&](int kt) {
        const int k0 = kt << 4;
#pragma unroll
        for (int j = 0; j < 2; ++j) {
            int i = tid + (j << 8);
            int ar = i >> 2, ac = (i & 3) << 2;
            aR[j] = *(const float4*)(A + (size_t)(bm + ar) * lda + k0 + ac);
            int br = i >> 5, bc = (i & 31) << 2;
            bR[j] = *(const float4*)(B + (size_t)(k0 + br) * ldb + bn + bc);
        }
    };
    auto storeTile = [&]() {
#pragma unroll
        for (int j = 0; j < 2; ++j) {
            int i = tid + (j << 8);
            int ar = i >> 2, ac = (i & 3) << 2;
            As[ac + 0][ar] = aR[j].x;
            As[ac + 1][ar] = aR[j].y;
            As[ac + 2][ar] = aR[j].z;
            As[ac + 3][ar] = aR[j].w;
            int br = i >> 5, bc = (i & 31) << 2;
            *(float4*)&Bs[br][bc] = bR[j];
        }
    };
    loadTile(0);
    storeTile();
    __syncthreads();
    for (int kt = 0; kt < nk; ++kt) {
        if (kt + 1 < nk) loadTile(kt + 1);
#pragma unroll
        for (int k = 0; k < 16; ++k) {
            float4 a0 = *(const float4*)&As[k][tm];
            float4 a1 = *(const float4*)&As[k][tm + 4];
            float4 b0 = *(const float4*)&Bs[k][tn];
            float4 b1 = *(const float4*)&Bs[k][tn + 4];
            unsigned long long rbp[4] = {pk2(b0.x, b0.y), pk2(b0.z, b0.w),
                                         pk2(b1.x, b1.y), pk2(b1.z, b1.w)};
            float ra[8] = {a0.x, a0.y, a0.z, a0.w, a1.x, a1.y, a1.z, a1.w};
#pragma unroll
            for (int i = 0; i < 8; ++i) {
                unsigned long long aa = pk2(ra[i], ra[i]);
#pragma unroll
                for (int jp = 0; jp < 4; ++jp) fma2(acc2[i][jp], aa, rbp[jp]);
            }
        }
        __syncthreads();
        if (kt + 1 < nk) {
            storeTile();
            __syncthreads();
        }
    }
    float bl[8];
#pragma unroll
    for (int j = 0; j < 8; ++j) bl[j] = bias ? bias[bn + tn + j] : 0.0f;
#pragma unroll
    for (int i = 0; i < 8; ++i) {
        float* crow = C + (size_t)(bm + tm + i) * ldc + bn + tn;
        float o[8];
#pragma unroll
        for (int jp = 0; jp < 4; ++jp) {
            float2 f = upk(acc2[i][jp]);
            o[2 * jp + 0] = f.x + bl[2 * jp + 0];
            o[2 * jp + 1] = f.y + bl[2 * jp + 1];
        }
        if (accumulate) {
            float4 c0 = *(const float4*)crow;
            float4 c1 = *(const float4*)(crow + 4);
            o[0] += c0.x; o[1] += c0.y; o[2] += c0.z; o[3] += c0.w;
            o[4] += c1.x; o[5] += c1.y; o[6] += c1.z; o[7] += c1.w;
        }
        *(float4*)crow = make_float4(o[0], o[1], o[2], o[3]);
        *(float4*)(crow + 4) = make_float4(o[4], o[5], o[6], o[7]);
    }
}

// ---------------------------------------------------------------------------
// Spatial attention — writes fp16 output directly (only consumer is fp16 GEMM)
// ---------------------------------------------------------------------------
__global__ __launch_bounds__(256) void spatial_attn(
    const float* __restrict__ Q, const float* __restrict__ Kp,
    const float* __restrict__ Vp, const int* __restrict__ mask,
    __half* __restrict__ O)
{
    int unit = blockIdx.x * 2 + (threadIdx.x >> 7);
    int t = threadIdx.x & 127;
    int h = t >> 3, qi = t & 7;
    int b = unit >> 8, nc = unit & 255;
    size_t rowBase = (size_t)b * SS + (size_t)nc * CLIPC;

    unsigned long long qv[32];
    {
        const unsigned long long* qp =
            (const unsigned long long*)(Q + (rowBase + qi) * DD + h * DK);
#pragma unroll
        for (int i = 0; i < 32; ++i) qv[i] = qp[i];
    }
    const float* kbase = Kp + rowBase * DD + h * DK;
    float sc[8];
    float mx = -1e30f;
#pragma unroll
    for (int kk = 0; kk < 8; ++kk) {
        const unsigned long long* kr =
            (const unsigned long long*)(kbase + (size_t)kk * DD);
        unsigned long long d2 = 0ull;
#pragma unroll
        for (int i = 0; i < 32; ++i) fma2(d2, qv[i], kr[i]);
        float2 dd = upk(d2);
        float s = (dd.x + dd.y) * 0.125f;
        sc[kk] = (mask[rowBase + kk] != 0) ? s : -1e30f;
        mx = fmaxf(mx, sc[kk]);
    }
    float p[8], sum = 0.f;
#pragma unroll
    for (int kk = 0; kk < 8; ++kk) {
        p[kk] = __expf(sc[kk] - mx);
        sum += p[kk];
    }
    float inv = 1.0f / sum;
    unsigned long long acc[32];
#pragma unroll
    for (int i = 0; i < 32; ++i) acc[i] = 0ull;
    const float* vbase = Vp + rowBase * DD + h * DK;
#pragma unroll
    for (int kk = 0; kk < 8; ++kk) {
        unsigned long long pp = pk2(p[kk], p[kk]);
        const unsigned long long* vr =
            (const unsigned long long*)(vbase + (size_t)kk * DD);
#pragma unroll
        for (int i = 0; i < 32; ++i) fma2(acc[i], pp, vr[i]);
    }
    __half2* op = (__half2*)(O + (rowBase + qi) * DD + h * DK);
#pragma unroll
    for (int i = 0; i < 32; ++i) {
        float2 f = upk(acc[i]);
        op[i] = __floats2half2_rn(f.x * inv, f.y * inv);
    }
}

// ---------------------------------------------------------------------------
// Temporal attention — writes fp16 output directly
// ---------------------------------------------------------------------------
__global__ __launch_bounds__(256) void temporal_attn(
    const float* __restrict__ Q, const float* __restrict__ Kp,
    const float* __restrict__ Vp, const int* __restrict__ mask,
    __half* __restrict__ O)
{
    __shared__ float Ks[64][64];
    __shared__ float Vs[64][64];
    __shared__ int Msk[64];

    int gid = blockIdx.x;
    int h = gid & 15;
    int clip = (gid >> 4) & 7;
    int b = gid >> 7;
    const size_t base = ((size_t)b * SS + clip) * DD + h * DK;
    const int RS = CLIPC * DD;

    int cq = threadIdx.x;
    unsigned long long qv[32];
    {
        const unsigned long long* qp =
            (const unsigned long long*)(Q + base + (size_t)cq * RS);
#pragma unroll
        for (int i = 0; i < 32; ++i) qv[i] = qp[i];
    }
    unsigned long long acc[32];
#pragma unroll
    for (int i = 0; i < 32; ++i) acc[i] = 0ull;
    float mmax = -1e30f, l = 0.f;

    const int lr = threadIdx.x >> 2;
    const int lc = (threadIdx.x & 3) << 4;

    for (int kt = 0; kt < 4; ++kt) {
        __syncthreads();
        {
            const float* krow = Kp + base + (size_t)(kt * 64 + lr) * RS;
            const float* vrow = Vp + base + (size_t)(kt * 64 + lr) * RS;
#pragma unroll
            for (int j = 0; j < 4; ++j) {
                *(float4*)&Ks[lr][lc + 4 * j] = *(const float4*)(krow + lc + 4 * j);
                *(float4*)&Vs[lr][lc + 4 * j] = *(const float4*)(vrow + lc + 4 * j);
            }
            if (threadIdx.x < 64)
                Msk[threadIdx.x] =
                    mask[(size_t)b * SS + (size_t)(kt * 64 + threadIdx.x) * CLIPC + clip];
        }
        __syncthreads();

        for (int kk = 0; kk < 64; ++kk) {
            if (Msk[kk] == 0) continue;
            const unsigned long long* kr = (const unsigned long long*)&Ks[kk][0];
            unsigned long long d2 = 0ull;
#pragma unroll
            for (int i = 0; i < 32; ++i) fma2(d2, qv[i], kr[i]);
            float2 dd = upk(d2);
            float s = (dd.x + dd.y) * 0.125f;
            if (s > mmax) {
                float corr = __expf(mmax - s);
                unsigned long long cc = pk2(corr, corr);
#pragma unroll
                for (int i = 0; i < 32; ++i) mul2(acc[i], cc);
                l *= corr;
                mmax = s;
            }
            float p = __expf(s - mmax);
            l += p;
            unsigned long long pp = pk2(p, p);
            const unsigned long long* vr = (const unsigned long long*)&Vs[kk][0];
#pragma unroll
            for (int i = 0; i < 32; ++i) fma2(acc[i], pp, vr[i]);
        }
    }
    float inv = 1.0f / l;
    __half2* op = (__half2*)(O + base + (size_t)cq * RS);
#pragma unroll
    for (int i = 0; i < 32; ++i) {
        float2 f = upk(acc[i]);
        op[i] = __floats2half2_rn(f.x * inv, f.y * inv);
    }
}

// ---------------------------------------------------------------------------
// bias combine, parallel 2-stage
// ---------------------------------------------------------------------------
__global__ void bias_partial(const float* __restrict__ sab,
                             const float* __restrict__ tab,
                             const float* __restrict__ fw,
                             float* __restrict__ part)
{
    int n = blockIdx.x * 256 + threadIdx.x;
    int j = blockIdx.y;
    int k0 = j * 64;
    float s = 0.f;
#pragma unroll 8
    for (int k = k0; k < k0 + 64; ++k) {
        float coef = (k < DD) ? sab[k] : tab[k - DD];
        s += coef * fw[(size_t)k * DD + n];
    }
    part[(size_t)j * DD + n] = s;
}

__global__ void bias_reduce(const float* __restrict__ part,
                            const float* __restrict__ fb,
                            float* __restrict__ bc)
{
    int n = blockIdx.x * 256 + threadIdx.x;
    float s = fb[n];
#pragma unroll
    for (int j = 0; j < 32; ++j) s += part[(size_t)j * DD + n];
    bc[n] = s;
}

// ---------------------------------------------------------------------------
// Launch sequence
// ---------------------------------------------------------------------------
extern "C" void kernel_launch(void* const* d_in, const int* in_sizes, int n_in,
                              void* d_out, int out_size)
{
    const float* x       = (const float*)d_in[0];
    const int*   mask    = (const int*)d_in[1];
    const float* sa_q_w  = (const float*)d_in[2];
    const float* sa_q_b  = (const float*)d_in[3];
    const float* sa_k_w  = (const float*)d_in[4];
    const float* sa_k_b  = (const float*)d_in[5];
    const float* sa_v_w  = (const float*)d_in[6];
    const float* sa_v_b  = (const float*)d_in[7];
    const float* sa_o_w  = (const float*)d_in[8];
    const float* sa_o_b  = (const float*)d_in[9];
    const float* ta_q_w  = (const float*)d_in[10];
    const float* ta_q_b  = (const float*)d_in[11];
    const float* ta_k_w  = (const float*)d_in[12];
    const float* ta_k_b  = (const float*)d_in[13];
    const float* ta_v_w  = (const float*)d_in[14];
    const float* ta_v_b  = (const float*)d_in[15];
    const float* ta_o_w  = (const float*)d_in[16];
    const float* ta_o_b  = (const float*)d_in[17];
    const float* fuse_w  = (const float*)d_in[18];
    const float* fuse_b  = (const float*)d_in[19];
    float* out = (float*)d_out;

    float *qs, *ks, *vs, *qt, *kt, *vt, *W1, *W2, *bc, *bcp;
    cudaGetSymbolAddress((void**)&qs, g_qs);
    cudaGetSymbolAddress((void**)&ks, g_ks);
    cudaGetSymbolAddress((void**)&vs, g_vs);
    cudaGetSymbolAddress((void**)&qt, g_qt);
    cudaGetSymbolAddress((void**)&kt, g_kt);
    cudaGetSymbolAddress((void**)&vt, g_vt);
    cudaGetSymbolAddress((void**)&W1, g_W1);
    cudaGetSymbolAddress((void**)&W2, g_W2);
    cudaGetSymbolAddress((void**)&bc, g_bc);
    cudaGetSymbolAddress((void**)&bcp, g_bcp);

    __half *xh, *csh, *cth, *wth, *wtl;
    cudaGetSymbolAddress((void**)&xh, g_xh);
    cudaGetSymbolAddress((void**)&csh, g_csh);
    cudaGetSymbolAddress((void**)&cth, g_cth);
    cudaGetSymbolAddress((void**)&wth, g_wth);
    cudaGetSymbolAddress((void**)&wtl, g_wtl);
    const size_t WSZ = (size_t)DD * DD;

    cudaFuncSetAttribute(mma_gemm_qkv, cudaFuncAttributeMaxDynamicSharedMemorySize,
                         SMEM_DYN);
    cudaFuncSetAttribute(mma_gemm_dual, cudaFuncAttributeMaxDynamicSharedMemorySize,
                         SMEM_DYN);

    const int nBlkCvt = MROWS * DD / 4 / 256;  // 32768

    // 1) convert x to fp16
    cvt_half<<<nBlkCvt, 256>>>((const float4*)x, xh);

    // 2) fold o-proj into fuse (fp32 scalar, small), combine biases
    dim3 gSm(DD / 128, DD / 128);
    gemm_kernel<<<gSm, 256>>>(sa_o_w, fuse_w, nullptr, W1, DD, DD, DD, DD, DD, DD, 0);
    gemm_kernel<<<gSm, 256>>>(ta_o_w, fuse_w + WSZ, nullptr, W2, DD, DD, DD, DD, DD, DD, 0);
    bias_partial<<<dim3(4, 32), 256>>>(sa_o_b, ta_o_b, fuse_w, bcp);
    bias_reduce<<<4, 256>>>(bcp, fuse_b, bc);

    // 3) transpose + split all B-operand weights
    dim3 gT(32, 32), bT(32, 8);
    wt_split<<<gT, bT>>>(sa_q_w, wth + 0 * WSZ, wtl + 0 * WSZ);
    wt_split<<<gT, bT>>>(sa_k_w, wth + 1 * WSZ, wtl + 1 * WSZ);
    wt_split<<<gT, bT>>>(sa_v_w, wth + 2 * WSZ, wtl + 2 * WSZ);
    wt_split<<<gT, bT>>>(ta_q_w, wth + 3 * WSZ, wtl + 3 * WSZ);
    wt_split<<<gT, bT>>>(ta_k_w, wth + 4 * WSZ, wtl + 4 * WSZ);
    wt_split<<<gT, bT>>>(ta_v_w, wth + 5 * WSZ, wtl + 5 * WSZ);
    wt_split<<<gT, bT>>>(W1, wth + 6 * WSZ, wtl + 6 * WSZ);
    wt_split<<<gT, bT>>>(W2, wth + 7 * WSZ, wtl + 7 * WSZ);

    // 4) six QKV projections on tensor cores (batched over z)
    QkvPtrs qp;
    float* outs[6] = {qs, ks, vs, qt, kt, vt};
    const float* biases[6] = {sa_q_b, sa_k_b, sa_v_b, ta_q_b, ta_k_b, ta_v_b};
    for (int i = 0; i < 6; ++i) {
        qp.Bh[i] = wth + i * WSZ;
        qp.Bl[i] = wtl + i * WSZ;
        qp.bias[i] = biases[i];
        qp.C[i] = outs[i];
    }
    mma_gemm_qkv<<<dim3(DD / 128, MROWS / 128, 6), 256, SMEM_DYN>>>(xh, qp);

    // 5) attention (writes fp16 directly)
    spatial_attn<<<BB * NCC / 2, 256>>>(qs, ks, vs, mask, csh);
    temporal_attn<<<BB * CLIPC * HH, 256>>>(qt, kt, vt, mask, cth);

    // 6) fused output: out = cs@W1t + ct@W2t + bc (single dual-K tensor GEMM)
    mma_gemm_dual<<<dim3(DD / 128, MROWS / 128), 256, SMEM_DYN>>>(
        csh, wth + 6 * WSZ, wtl + 6 * WSZ,
        cth, wth + 7 * WSZ, wtl + 7 * WSZ,
        bc, out);
}

// round 8
// speedup vs baseline: 1.0998x; 1.0998x over previous
#include <cuda_runtime.h>
#include <cuda_fp16.h>
#include <cstdint>

// Problem constants
#define BB 16
#define SS 2048
#define DD 1024
#define HH 16
#define DK 64
#define CLIPC 8
#define NCC 256
#define MROWS (BB * SS)  // 32768

// ---------------------------------------------------------------------------
// Scratch (static __device__ arrays; no allocation allowed)
// ---------------------------------------------------------------------------
__device__ float g_qs[MROWS * DD];
__device__ float g_ks[MROWS * DD];
__device__ float g_vs[MROWS * DD];
__device__ float g_qt[MROWS * DD];
__device__ float g_kt[MROWS * DD];
__device__ float g_vt[MROWS * DD];
__device__ float g_W1[DD * DD];
__device__ float g_W2[DD * DD];
__device__ float g_bc[DD];
__device__ float g_bcp[32][DD];

// fp16 buffers (A operands: hi only; weights: hi+lo)
__device__ __half g_xh[MROWS * DD];
__device__ __half g_csh[MROWS * DD];   // spatial attention out (fp16, direct)
__device__ __half g_cth[MROWS * DD];   // temporal attention out (fp16, direct)
// transposed+split weights: 0..5 = sa_q,sa_k,sa_v,ta_q,ta_k,ta_v; 6=W1; 7=W2
__device__ __half g_wth[8][DD * DD];
__device__ __half g_wtl[8][DD * DD];

// ---------------------------------------------------------------------------
// Packed f32x2 helpers
// ---------------------------------------------------------------------------
__device__ __forceinline__ unsigned long long pk2(float lo, float hi) {
    unsigned long long r;
    asm("mov.b64 %0, {%1, %2};" : "=l"(r) : "f"(lo), "f"(hi));
    return r;
}
__device__ __forceinline__ void fma2(unsigned long long& d, unsigned long long a,
                                     unsigned long long b) {
    asm("fma.rn.f32x2 %0, %1, %2, %0;" : "+l"(d) : "l"(a), "l"(b));
}
__device__ __forceinline__ void mul2(unsigned long long& d, unsigned long long a) {
    asm("mul.rn.f32x2 %0, %0, %1;" : "+l"(d) : "l"(a));
}
__device__ __forceinline__ float2 upk(unsigned long long v) {
    float2 f;
    asm("mov.b64 {%0, %1}, %2;" : "=f"(f.x), "=f"(f.y) : "l"(v));
    return f;
}

// ---------------------------------------------------------------------------
// mma.sync helpers (base PTX ISA — compiles at .target sm_103)
// ---------------------------------------------------------------------------
__device__ __forceinline__ uint32_t smem_u32(const void* p) {
    uint32_t a;
    asm("{ .reg .u64 t; cvta.to.shared.u64 t, %1; cvt.u32.u64 %0, t; }"
        : "=r"(a) : "l"(p));
    return a;
}
__device__ __forceinline__ void ldsm4(uint32_t* r, uint32_t addr) {
    asm volatile(
        "ldmatrix.sync.aligned.m8n8.x4.shared.b16 {%0,%1,%2,%3}, [%4];"
        : "=r"(r[0]), "=r"(r[1]), "=r"(r[2]), "=r"(r[3]) : "r"(addr));
}
__device__ __forceinline__ void mma16816(float* d, const uint32_t* a,
                                         const uint32_t* b) {
    asm volatile(
        "mma.sync.aligned.m16n8k16.row.col.f32.f16.f16.f32 "
        "{%0,%1,%2,%3}, {%4,%5,%6,%7}, {%8,%9}, {%0,%1,%2,%3};"
        : "+f"(d[0]), "+f"(d[1]), "+f"(d[2]), "+f"(d[3])
        : "r"(a[0]), "r"(a[1]), "r"(a[2]), "r"(a[3]), "r"(b[0]), "r"(b[1]));
}
#define CPASYNC16(dst, src) \
    asm volatile("cp.async.cg.shared.global [%0], [%1], 16;" :: "r"(dst), "l"(src))
#define CPCOMMIT() asm volatile("cp.async.commit_group;" ::: "memory")
#define CPWAIT2() asm volatile("cp.async.wait_group 2;" ::: "memory")

// smem geometry: row pitch 80B (40 fp16). 80 = 5*16, so the 8 rows of any
// ldmatrix 8x8 (stride 80B) hit 8 distinct 16B bank groups -> conflict-free.
#define PITCHB 80
#define TILEB (128 * PITCHB)     // 10240 bytes per operand tile
#define STAGEB (3 * TILEB)       // Ah, Bh, Bl
#define NSTAGE 3
#define SMEM_DYN (NSTAGE * STAGEB)  // 92160 bytes

// ---------------------------------------------------------------------------
// fp16 2-pass GEMM core: C = Ah*Bh^T + Ah*Bl^T + bias
//   (== Ah*(Wh+Wl)^T; dropped term lo(A)*W ~ 2^-12 relative)
// A [M,1024] fp16 row-major, Bt [N=1024,K=1024] fp16 [N,K] (pre-transposed).
// CTA tile 128x128, BK=32, 256 thr = 8 warps (4 M x 2 N), warp tile 32x64.
// 3-stage cp.async pipeline.  (R4-proven config — measured 5057us total)
// ---------------------------------------------------------------------------
struct GSrc {
    const __half *Ah, *Bh, *Bl;
};

__device__ __forceinline__ void mma_core(
    GSrc s0, GSrc s1, int nchunk,
    const float* __restrict__ bias, float* __restrict__ C, int bm, int bn)
{
    extern __shared__ char sm[];
    const uint32_t sbase = smem_u32(sm);
    const int tid = threadIdx.x, wid = tid >> 5, l = tid & 31;
    const int wm = (wid & 3) * 32;   // warp row offset in CTA tile
    const int wn = (wid >> 2) * 64;  // warp col offset

    // stage copy: 3 tiles x 512 16B-chunks, 2 chunks per thread per tile
    auto issue = [&](int kc) {
        if (kc < nchunk) {
            const GSrc& s = (kc < 32) ? s0 : s1;
            const int kl = kc & 31;
            const uint32_t st = sbase + (kc % NSTAGE) * STAGEB;
            const __half* srcs[3] = {s.Ah, s.Bh, s.Bl};
#pragma unroll
            for (int t3 = 0; t3 < 3; ++t3) {
                const int rb = (t3 == 0) ? bm : bn;
                const uint32_t doff = st + t3 * TILEB;
                const __half* sp = srcs[t3];
#pragma unroll
                for (int j = 0; j < 2; ++j) {
                    int c = tid + j * 256;
                    int row = c >> 2, pos = c & 3;
                    uint32_t dst = doff + row * PITCHB + pos * 16;
                    const void* src = sp + (size_t)(rb + row) * DD + kl * 32 + pos * 8;
                    CPASYNC16(dst, src);
                }
            }
        }
        CPCOMMIT();
    };

    issue(0);
    issue(1);
    issue(2);

    float acc[2][8][4];
#pragma unroll
    for (int mi = 0; mi < 2; ++mi)
#pragma unroll
        for (int ni = 0; ni < 8; ++ni)
#pragma unroll
            for (int f = 0; f < 4; ++f) acc[mi][ni][f] = 0.0f;

    // ldmatrix per-lane addressing (m = l/8 selects the 8x8 matrix)
    const uint32_t m8 = l >> 3;
    const uint32_t laneArow = (m8 & 1) * 8 + (l & 7);
    const uint32_t laneAkb = (m8 >> 1) * 16;
    const uint32_t laneBrow = (m8 >> 1) * 8 + (l & 7);
    const uint32_t laneBkb = (m8 & 1) * 16;

    for (int kc = 0; kc < nchunk; ++kc) {
        CPWAIT2();
        __syncthreads();
        const uint32_t st = sbase + (kc % NSTAGE) * STAGEB;
#pragma unroll
        for (int ks = 0; ks < 2; ++ks) {
            const uint32_t kbyte = ks * 32;
            uint32_t ah[2][4];
#pragma unroll
            for (int mi = 0; mi < 2; ++mi) {
                uint32_t r = wm + mi * 16 + laneArow;
                ldsm4(ah[mi], st + 0 * TILEB + r * PITCHB + kbyte + laneAkb);
            }
            uint32_t bh[8][2], bl[8][2];
#pragma unroll
            for (int bi = 0; bi < 4; ++bi) {
                uint32_t r = wn + bi * 16 + laneBrow;
                uint32_t q[4];
                ldsm4(q, st + 1 * TILEB + r * PITCHB + kbyte + laneBkb);
                bh[bi * 2][0] = q[0]; bh[bi * 2][1] = q[1];
                bh[bi * 2 + 1][0] = q[2]; bh[bi * 2 + 1][1] = q[3];
                ldsm4(q, st + 2 * TILEB + r * PITCHB + kbyte + laneBkb);
                bl[bi * 2][0] = q[0]; bl[bi * 2][1] = q[1];
                bl[bi * 2 + 1][0] = q[2]; bl[bi * 2 + 1][1] = q[3];
            }
#pragma unroll
            for (int mi = 0; mi < 2; ++mi)
#pragma unroll
                for (int ni = 0; ni < 8; ++ni) {
                    mma16816(acc[mi][ni], ah[mi], bh[ni]);
                    mma16816(acc[mi][ni], ah[mi], bl[ni]);
                }
        }
        __syncthreads();
        issue(kc + NSTAGE);
    }

    // epilogue: acc frag f: rows l/4 (+8 for f>=2), cols (l%4)*2 + (f&1)
#pragma unroll
    for (int mi = 0; mi < 2; ++mi) {
        const int r0 = bm + wm + mi * 16 + (l >> 2);
#pragma unroll
        for (int ni = 0; ni < 8; ++ni) {
            const int c = bn + wn + ni * 8 + (l & 3) * 2;
            const float b0v = bias[c], b1v = bias[c + 1];
            float2 v0, v1;
            v0.x = acc[mi][ni][0] + b0v;
            v0.y = acc[mi][ni][1] + b1v;
            v1.x = acc[mi][ni][2] + b0v;
            v1.y = acc[mi][ni][3] + b1v;
            *(float2*)(C + (size_t)r0 * DD + c) = v0;
            *(float2*)(C + (size_t)(r0 + 8) * DD + c) = v1;
        }
    }
}

// batched QKV: z selects weight/bias/output; A = x (shared)
struct QkvPtrs {
    const __half* Bh[6];
    const __half* Bl[6];
    const float* bias[6];
    float* C[6];
};

__global__ __launch_bounds__(256) void mma_gemm_qkv(
    const __half* __restrict__ Ah, QkvPtrs p)
{
    int z = blockIdx.z;
    GSrc s{Ah, p.Bh[z], p.Bl[z]};
    mma_core(s, s, 32, p.bias[z], p.C[z], blockIdx.y * 128, blockIdx.x * 128);
}

__global__ __launch_bounds__(256) void mma_gemm_dual(
    const __half* A0h, const __half* B0h, const __half* B0l,
    const __half* A1h, const __half* B1h, const __half* B1l,
    const float* bias, float* C)
{
    GSrc s0{A0h, B0h, B0l};
    GSrc s1{A1h, B1h, B1l};
    mma_core(s0, s1, 64, bias, C, blockIdx.y * 128, blockIdx.x * 128);
}

// ---------------------------------------------------------------------------
// fp32 -> fp16 convert (hi only), vectorized
// ---------------------------------------------------------------------------
__global__ __launch_bounds__(256) void cvt_half(
    const float4* __restrict__ X, __half* __restrict__ H)
{
    size_t idx = (size_t)blockIdx.x * 256 + threadIdx.x;
    float4 v = X[idx];
    __half h[4];
    h[0] = __float2half(v.x);
    h[1] = __float2half(v.y);
    h[2] = __float2half(v.z);
    h[3] = __float2half(v.w);
    *(uint2*)(H + idx * 4) = *(uint2*)h;
}

// ---------------------------------------------------------------------------
// Weight transpose + split: W[K=1024, N=1024] fp32 -> Th/Tl [N,K] fp16
// ---------------------------------------------------------------------------
__global__ __launch_bounds__(256) void wt_split(
    const float* __restrict__ W, __half* __restrict__ Th,
    __half* __restrict__ Tl)
{
    __shared__ float t[32][33];
    int tx = threadIdx.x, ty = threadIdx.y;
    int n0 = blockIdx.x * 32, k0 = blockIdx.y * 32;
#pragma unroll
    for (int j = 0; j < 4; ++j) {
        int k = k0 + ty + j * 8;
        t[ty + j * 8][tx] = W[(size_t)k * DD + n0 + tx];
    }
    __syncthreads();
#pragma unroll
    for (int j = 0; j < 4; ++j) {
        int n = n0 + ty + j * 8;
        int k = k0 + tx;
        float v = t[tx][ty + j * 8];
        __half h = __float2half(v);
        __half lo = __float2half(v - __half2float(h));
        Th[(size_t)n * DD + k] = h;
        Tl[(size_t)n * DD + k] = lo;
    }
}

// ---------------------------------------------------------------------------
// Scalar fp32 GEMM (kept for the two small 1024x1024x1024 weight folds)
// ---------------------------------------------------------------------------
__global__ __launch_bounds__(256) void gemm_kernel(
    const float* __restrict__ A, const float* __restrict__ B,
    const float* __restrict__ bias, float* __restrict__ C,
    int M, int N, int K, int lda, int ldb, int ldc, int accumulate)
{
    __shared__ float As[16][128];
    __shared__ float Bs[16][128];
    const int tid = threadIdx.x;
    const int bm = blockIdx.y * 128;
    const int bn = blockIdx.x * 128;
    const int tm = (tid >> 4) << 3;
    const int tn = (tid & 15) << 3;

    unsigned long long acc2[8][4];
#pragma unroll
    for (int i = 0; i < 8; ++i)
#pragma unroll
        for (int j = 0; j < 4; ++j) acc2[i][j] = 0ull;

    const int nk = K >> 4;
    float4 aR[2], bR[2];
    auto loadTile = [&](int kt) {
        const int k0 = kt << 4;
#pragma unroll
        for (int j = 0; j < 2; ++j) {
            int i = tid + (j << 8);
            int ar = i >> 2, ac = (i & 3) << 2;
            aR[j] = *(const float4*)(A + (size_t)(bm + ar) * lda + k0 + ac);
            int br = i >> 5, bc = (i & 31) << 2;
            bR[j] = *(const float4*)(B + (size_t)(k0 + br) * ldb + bn + bc);
        }
    };
    auto storeTile = [&]() {
#pragma unroll
        for (int j = 0; j < 2; ++j) {
            int i = tid + (j << 8);
            int ar = i >> 2, ac = (i & 3) << 2;
            As[ac + 0][ar] = aR[j].x;
            As[ac + 1][ar] = aR[j].y;
            As[ac + 2][ar] = aR[j].z;
            As[ac + 3][ar] = aR[j].w;
            int br = i >> 5, bc = (i & 31) << 2;
            *(float4*)&Bs[br][bc] = bR[j];
        }
    };
    loadTile(0);
    storeTile();
    __syncthreads();
    for (int kt = 0; kt < nk; ++kt) {
        if (kt + 1 < nk) loadTile(kt + 1);
#pragma unroll
        for (int k = 0; k < 16; ++k) {
            float4 a0 = *(const float4*)&As[k][tm];
            float4 a1 = *(const float4*)&As[k][tm + 4];
            float4 b0 = *(const float4*)&Bs[k][tn];
            float4 b1 = *(const float4*)&Bs[k][tn + 4];
            unsigned long long rbp[4] = {pk2(b0.x, b0.y), pk2(b0.z, b0.w),
                                         pk2(b1.x, b1.y), pk2(b1.z, b1.w)};
            float ra[8] = {a0.x, a0.y, a0.z, a0.w, a1.x, a1.y, a1.z, a1.w};
#pragma unroll
            for (int i = 0; i < 8; ++i) {
                unsigned long long aa = pk2(ra[i], ra[i]);
#pragma unroll
                for (int jp = 0; jp < 4; ++jp) fma2(acc2[i][jp], aa, rbp[jp]);
            }
        }
        __syncthreads();
        if (kt + 1 < nk) {
            storeTile();
            __syncthreads();
        }
    }
    float bl[8];
#pragma unroll
    for (int j = 0; j < 8; ++j) bl[j] = bias ? bias[bn + tn + j] : 0.0f;
#pragma unroll
    for (int i = 0; i < 8; ++i) {
        float* crow = C + (size_t)(bm + tm + i) * ldc + bn + tn;
        float o[8];
#pragma unroll
        for (int jp = 0; jp < 4; ++jp) {
            float2 f = upk(acc2[i][jp]);
            o[2 * jp + 0] = f.x + bl[2 * jp + 0];
            o[2 * jp + 1] = f.y + bl[2 * jp + 1];
        }
        if (accumulate) {
            float4 c0 = *(const float4*)crow;
            float4 c1 = *(const float4*)(crow + 4);
            o[0] += c0.x; o[1] += c0.y; o[2] += c0.z; o[3] += c0.w;
            o[4] += c1.x; o[5] += c1.y; o[6] += c1.z; o[7] += c1.w;
        }
        *(float4*)crow = make_float4(o[0], o[1], o[2], o[3]);
        *(float4*)(crow + 4) = make_float4(o[4], o[5], o[6], o[7]);
    }
}

// ---------------------------------------------------------------------------
// Spatial attention — writes fp16 output directly (only consumer is fp16 GEMM)
// ---------------------------------------------------------------------------
__global__ __launch_bounds__(256) void spatial_attn(
    const float* __restrict__ Q, const float* __restrict__ Kp,
    const float* __restrict__ Vp, const int* __restrict__ mask,
    __half* __restrict__ O)
{
    int unit = blockIdx.x * 2 + (threadIdx.x >> 7);
    int t = threadIdx.x & 127;
    int h = t >> 3, qi = t & 7;
    int b = unit >> 8, nc = unit & 255;
    size_t rowBase = (size_t)b * SS + (size_t)nc * CLIPC;

    unsigned long long qv[32];
    {
        const unsigned long long* qp =
            (const unsigned long long*)(Q + (rowBase + qi) * DD + h * DK);
#pragma unroll
        for (int i = 0; i < 32; ++i) qv[i] = qp[i];
    }
    const float* kbase = Kp + rowBase * DD + h * DK;
    float sc[8];
    float mx = -1e30f;
#pragma unroll
    for (int kk = 0; kk < 8; ++kk) {
        const unsigned long long* kr =
            (const unsigned long long*)(kbase + (size_t)kk * DD);
        unsigned long long d2 = 0ull;
#pragma unroll
        for (int i = 0; i < 32; ++i) fma2(d2, qv[i], kr[i]);
        float2 dd = upk(d2);
        float s = (dd.x + dd.y) * 0.125f;
        sc[kk] = (mask[rowBase + kk] != 0) ? s : -1e30f;
        mx = fmaxf(mx, sc[kk]);
    }
    float p[8], sum = 0.f;
#pragma unroll
    for (int kk = 0; kk < 8; ++kk) {
        p[kk] = __expf(sc[kk] - mx);
        sum += p[kk];
    }
    float inv = 1.0f / sum;
    unsigned long long acc[32];
#pragma unroll
    for (int i = 0; i < 32; ++i) acc[i] = 0ull;
    const float* vbase = Vp + rowBase * DD + h * DK;
#pragma unroll
    for (int kk = 0; kk < 8; ++kk) {
        unsigned long long pp = pk2(p[kk], p[kk]);
        const unsigned long long* vr =
            (const unsigned long long*)(vbase + (size_t)kk * DD);
#pragma unroll
        for (int i = 0; i < 32; ++i) fma2(acc[i], pp, vr[i]);
    }
    __half2* op = (__half2*)(O + (rowBase + qi) * DD + h * DK);
#pragma unroll
    for (int i = 0; i < 32; ++i) {
        float2 f = upk(acc[i]);
        op[i] = __floats2half2_rn(f.x * inv, f.y * inv);
    }
}

// ---------------------------------------------------------------------------
// Temporal attention — writes fp16 output directly
// ---------------------------------------------------------------------------
__global__ __launch_bounds__(256) void temporal_attn(
    const float* __restrict__ Q, const float* __restrict__ Kp,
    const float* __restrict__ Vp, const int* __restrict__ mask,
    __half* __restrict__ O)
{
    __shared__ float Ks[64][64];
    __shared__ float Vs[64][64];
    __shared__ int Msk[64];

    int gid = blockIdx.x;
    int h = gid & 15;
    int clip = (gid >> 4) & 7;
    int b = gid >> 7;
    const size_t base = ((size_t)b * SS + clip) * DD + h * DK;
    const int RS = CLIPC * DD;

    int cq = threadIdx.x;
    unsigned long long qv[32];
    {
        const unsigned long long* qp =
            (const unsigned long long*)(Q + base + (size_t)cq * RS);
#pragma unroll
        for (int i = 0; i < 32; ++i) qv[i] = qp[i];
    }
    unsigned long long acc[32];
#pragma unroll
    for (int i = 0; i < 32; ++i) acc[i] = 0ull;
    float mmax = -1e30f, l = 0.f;

    const int lr = threadIdx.x >> 2;
    const int lc = (threadIdx.x & 3) << 4;

    for (int kt = 0; kt < 4; ++kt) {
        __syncthreads();
        {
            const float* krow = Kp + base + (size_t)(kt * 64 + lr) * RS;
            const float* vrow = Vp + base + (size_t)(kt * 64 + lr) * RS;
#pragma unroll
            for (int j = 0; j < 4; ++j) {
                *(float4*)&Ks[lr][lc + 4 * j] = *(const float4*)(krow + lc + 4 * j);
                *(float4*)&Vs[lr][lc + 4 * j] = *(const float4*)(vrow + lc + 4 * j);
            }
            if (threadIdx.x < 64)
                Msk[threadIdx.x] =
                    mask[(size_t)b * SS + (size_t)(kt * 64 + threadIdx.x) * CLIPC + clip];
        }
        __syncthreads();

        for (int kk = 0; kk < 64; ++kk) {
            if (Msk[kk] == 0) continue;
            const unsigned long long* kr = (const unsigned long long*)&Ks[kk][0];
            unsigned long long d2 = 0ull;
#pragma unroll
            for (int i = 0; i < 32; ++i) fma2(d2, qv[i], kr[i]);
            float2 dd = upk(d2);
            float s = (dd.x + dd.y) * 0.125f;
            if (s > mmax) {
                float corr = __expf(mmax - s);
                unsigned long long cc = pk2(corr, corr);
#pragma unroll
                for (int i = 0; i < 32; ++i) mul2(acc[i], cc);
                l *= corr;
                mmax = s;
            }
            float p = __expf(s - mmax);
            l += p;
            unsigned long long pp = pk2(p, p);
            const unsigned long long* vr = (const unsigned long long*)&Vs[kk][0];
#pragma unroll
            for (int i = 0; i < 32; ++i) fma2(acc[i], pp, vr[i]);
        }
    }
    float inv = 1.0f / l;
    __half2* op = (__half2*)(O + base + (size_t)cq * RS);
#pragma unroll
    for (int i = 0; i < 32; ++i) {
        float2 f = upk(acc[i]);
        op[i] = __floats2half2_rn(f.x * inv, f.y * inv);
    }
}

// ---------------------------------------------------------------------------
// bias combine, parallel 2-stage
// ---------------------------------------------------------------------------
__global__ void bias_partial(const float* __restrict__ sab,
                             const float* __restrict__ tab,
                             const float* __restrict__ fw,
                             float* __restrict__ part)
{
    int n = blockIdx.x * 256 + threadIdx.x;
    int j = blockIdx.y;
    int k0 = j * 64;
    float s = 0.f;
#pragma unroll 8
    for (int k = k0; k < k0 + 64; ++k) {
        float coef = (k < DD) ? sab[k] : tab[k - DD];
        s += coef * fw[(size_t)k * DD + n];
    }
    part[(size_t)j * DD + n] = s;
}

__global__ void bias_reduce(const float* __restrict__ part,
                            const float* __restrict__ fb,
                            float* __restrict__ bc)
{
    int n = blockIdx.x * 256 + threadIdx.x;
    float s = fb[n];
#pragma unroll
    for (int j = 0; j < 32; ++j) s += part[(size_t)j * DD + n];
    bc[n] = s;
}

// ---------------------------------------------------------------------------
// Launch sequence
// ---------------------------------------------------------------------------
extern "C" void kernel_launch(void* const* d_in, const int* in_sizes, int n_in,
                              void* d_out, int out_size)
{
    const float* x       = (const float*)d_in[0];
    const int*   mask    = (const int*)d_in[1];
    const float* sa_q_w  = (const float*)d_in[2];
    const float* sa_q_b  = (const float*)d_in[3];
    const float* sa_k_w  = (const float*)d_in[4];
    const float* sa_k_b  = (const float*)d_in[5];
    const float* sa_v_w  = (const float*)d_in[6];
    const float* sa_v_b  = (const float*)d_in[7];
    const float* sa_o_w  = (const float*)d_in[8];
    const float* sa_o_b  = (const float*)d_in[9];
    const float* ta_q_w  = (const float*)d_in[10];
    const float* ta_q_b  = (const float*)d_in[11];
    const float* ta_k_w  = (const float*)d_in[12];
    const float* ta_k_b  = (const float*)d_in[13];
    const float* ta_v_w  = (const float*)d_in[14];
    const float* ta_v_b  = (const float*)d_in[15];
    const float* ta_o_w  = (const float*)d_in[16];
    const float* ta_o_b  = (const float*)d_in[17];
    const float* fuse_w  = (const float*)d_in[18];
    const float* fuse_b  = (const float*)d_in[19];
    float* out = (float*)d_out;

    float *qs, *ks, *vs, *qt, *kt, *vt, *W1, *W2, *bc, *bcp;
    cudaGetSymbolAddress((void**)&qs, g_qs);
    cudaGetSymbolAddress((void**)&ks, g_ks);
    cudaGetSymbolAddress((void**)&vs, g_vs);
    cudaGetSymbolAddress((void**)&qt, g_qt);
    cudaGetSymbolAddress((void**)&kt, g_kt);
    cudaGetSymbolAddress((void**)&vt, g_vt);
    cudaGetSymbolAddress((void**)&W1, g_W1);
    cudaGetSymbolAddress((void**)&W2, g_W2);
    cudaGetSymbolAddress((void**)&bc, g_bc);
    cudaGetSymbolAddress((void**)&bcp, g_bcp);

    __half *xh, *csh, *cth, *wth, *wtl;
    cudaGetSymbolAddress((void**)&xh, g_xh);
    cudaGetSymbolAddress((void**)&csh, g_csh);
    cudaGetSymbolAddress((void**)&cth, g_cth);
    cudaGetSymbolAddress((void**)&wth, g_wth);
    cudaGetSymbolAddress((void**)&wtl, g_wtl);
    const size_t WSZ = (size_t)DD * DD;

    cudaFuncSetAttribute(mma_gemm_qkv, cudaFuncAttributeMaxDynamicSharedMemorySize,
                         SMEM_DYN);
    cudaFuncSetAttribute(mma_gemm_dual, cudaFuncAttributeMaxDynamicSharedMemorySize,
                         SMEM_DYN);

    const int nBlkCvt = MROWS * DD / 4 / 256;  // 32768

    // 1) convert x to fp16
    cvt_half<<<nBlkCvt, 256>>>((const float4*)x, xh);

    // 2) fold o-proj into fuse (fp32 scalar, small), combine biases
    dim3 gSm(DD / 128, DD / 128);
    gemm_kernel<<<gSm, 256>>>(sa_o_w, fuse_w, nullptr, W1, DD, DD, DD, DD, DD, DD, 0);
    gemm_kernel<<<gSm, 256>>>(ta_o_w, fuse_w + WSZ, nullptr, W2, DD, DD, DD, DD, DD, DD, 0);
    bias_partial<<<dim3(4, 32), 256>>>(sa_o_b, ta_o_b, fuse_w, bcp);
    bias_reduce<<<4, 256>>>(bcp, fuse_b, bc);

    // 3) transpose + split all B-operand weights
    dim3 gT(32, 32), bT(32, 8);
    wt_split<<<gT, bT>>>(sa_q_w, wth + 0 * WSZ, wtl + 0 * WSZ);
    wt_split<<<gT, bT>>>(sa_k_w, wth + 1 * WSZ, wtl + 1 * WSZ);
    wt_split<<<gT, bT>>>(sa_v_w, wth + 2 * WSZ, wtl + 2 * WSZ);
    wt_split<<<gT, bT>>>(ta_q_w, wth + 3 * WSZ, wtl + 3 * WSZ);
    wt_split<<<gT, bT>>>(ta_k_w, wth + 4 * WSZ, wtl + 4 * WSZ);
    wt_split<<<gT, bT>>>(ta_v_w, wth + 5 * WSZ, wtl + 5 * WSZ);
    wt_split<<<gT, bT>>>(W1, wth + 6 * WSZ, wtl + 6 * WSZ);
    wt_split<<<gT, bT>>>(W2, wth + 7 * WSZ, wtl + 7 * WSZ);

    // 4) six QKV projections on tensor cores (batched over z)
    QkvPtrs qp;
    float* outs[6] = {qs, ks, vs, qt, kt, vt};
    const float* biases[6] = {sa_q_b, sa_k_b, sa_v_b, ta_q_b, ta_k_b, ta_v_b};
    for (int i = 0; i < 6; ++i) {
        qp.Bh[i] = wth + i * WSZ;
        qp.Bl[i] = wtl + i * WSZ;
        qp.bias[i] = biases[i];
        qp.C[i] = outs[i];
    }
    mma_gemm_qkv<<<dim3(DD / 128, MROWS / 128, 6), 256, SMEM_DYN>>>(xh, qp);

    // 5) attention (writes fp16 directly)
    spatial_attn<<<BB * NCC / 2, 256>>>(qs, ks, vs, mask, csh);
    temporal_attn<<<BB * CLIPC * HH, 256>>>(qt, kt, vt, mask, cth);

    // 6) fused output: out = cs@W1t + ct@W2t + bc (single dual-K tensor GEMM)
    mma_gemm_dual<<<dim3(DD / 128, MROWS / 128), 256, SMEM_DYN>>>(
        csh, wth + 6 * WSZ, wtl + 6 * WSZ,
        cth, wth + 7 * WSZ, wtl + 7 * WSZ,
        bc, out);
}

// round 9
// speedup vs baseline: 1.1489x; 1.0446x over previous
#include <cuda_runtime.h>
#include <cuda_fp16.h>
#include <cstdint>

// Problem constants
#define BB 16
#define SS 2048
#define DD 1024
#define HH 16
#define DK 64
#define CLIPC 8
#define NCC 256
#define MROWS (BB * SS)  // 32768

// ---------------------------------------------------------------------------
// Scratch (static __device__ arrays; no allocation allowed)
// ---------------------------------------------------------------------------
__device__ float g_qs[MROWS * DD];
__device__ float g_ks[MROWS * DD];
__device__ float g_vs[MROWS * DD];
__device__ float g_qt[MROWS * DD];
__device__ float g_kt[MROWS * DD];
__device__ float g_vt[MROWS * DD];
__device__ float g_W1[DD * DD];
__device__ float g_W2[DD * DD];
__device__ float g_bc[DD];
__device__ float g_bcp[32][DD];

// fp16 buffers (A operands: hi only; weights: hi+lo)
__device__ __half g_xh[MROWS * DD];
__device__ __half g_csh[MROWS * DD];   // spatial attention out (fp16, direct)
__device__ __half g_cth[MROWS * DD];   // temporal attention out (fp16, direct)
// transposed+split weights: 0..5 = sa_q,sa_k,sa_v,ta_q,ta_k,ta_v; 6=W1; 7=W2
__device__ __half g_wth[8][DD * DD];
__device__ __half g_wtl[8][DD * DD];

// ---------------------------------------------------------------------------
// Packed f32x2 helpers
// ---------------------------------------------------------------------------
__device__ __forceinline__ unsigned long long pk2(float lo, float hi) {
    unsigned long long r;
    asm("mov.b64 %0, {%1, %2};" : "=l"(r) : "f"(lo), "f"(hi));
    return r;
}
__device__ __forceinline__ void fma2(unsigned long long& d, unsigned long long a,
                                     unsigned long long b) {
    asm("fma.rn.f32x2 %0, %1, %2, %0;" : "+l"(d) : "l"(a), "l"(b));
}
__device__ __forceinline__ void mul2(unsigned long long& d, unsigned long long a) {
    asm("mul.rn.f32x2 %0, %0, %1;" : "+l"(d) : "l"(a));
}
__device__ __forceinline__ float2 upk(unsigned long long v) {
    float2 f;
    asm("mov.b64 {%0, %1}, %2;" : "=f"(f.x), "=f"(f.y) : "l"(v));
    return f;
}

// ---------------------------------------------------------------------------
// mma.sync helpers (base PTX ISA — compiles at .target sm_103)
// ---------------------------------------------------------------------------
__device__ __forceinline__ uint32_t smem_u32(const void* p) {
    uint32_t a;
    asm("{ .reg .u64 t; cvta.to.shared.u64 t, %1; cvt.u32.u64 %0, t; }"
        : "=r"(a) : "l"(p));
    return a;
}
__device__ __forceinline__ void ldsm4(uint32_t* r, uint32_t addr) {
    asm volatile(
        "ldmatrix.sync.aligned.m8n8.x4.shared.b16 {%0,%1,%2,%3}, [%4];"
        : "=r"(r[0]), "=r"(r[1]), "=r"(r[2]), "=r"(r[3]) : "r"(addr));
}
__device__ __forceinline__ void mma16816(float* d, const uint32_t* a,
                                         const uint32_t* b) {
    asm volatile(
        "mma.sync.aligned.m16n8k16.row.col.f32.f16.f16.f32 "
        "{%0,%1,%2,%3}, {%4,%5,%6,%7}, {%8,%9}, {%0,%1,%2,%3};"
        : "+f"(d[0]), "+f"(d[1]), "+f"(d[2]), "+f"(d[3])
        : "r"(a[0]), "r"(a[1]), "r"(a[2]), "r"(a[3]), "r"(b[0]), "r"(b[1]));
}
#define CPASYNC16(dst, src) \
    asm volatile("cp.async.cg.shared.global [%0], [%1], 16;" :: "r"(dst), "l"(src))
#define CPCOMMIT() asm volatile("cp.async.commit_group;" ::: "memory")
#define CPWAIT2() asm volatile("cp.async.wait_group 2;" ::: "memory")

// smem geometry: row pitch 80B (40 fp16). 80 = 5*16, so the 8 rows of any
// ldmatrix 8x8 (stride 80B) hit 8 distinct 16B bank groups -> conflict-free.
#define PITCHB 80
#define TILEB (128 * PITCHB)     // 10240 bytes per operand tile
#define STAGEB (3 * TILEB)       // Ah, Bh, Bl
#define NSTAGE 3
#define SMEM_DYN (NSTAGE * STAGEB)  // 92160 bytes

// ---------------------------------------------------------------------------
// fp16 2-pass GEMM core: C = Ah*Bh^T + Ah*Bl^T + bias
//   (== Ah*(Wh+Wl)^T; dropped term lo(A)*W ~ 2^-12 relative)
// A [M,1024] fp16 row-major, Bt [N=1024,K=1024] fp16 [N,K] (pre-transposed).
// CTA tile 128x128, BK=32, 256 thr = 8 warps (4 M x 2 N), warp tile 32x64.
// 3-stage cp.async pipeline.  (R4-proven config)
// ---------------------------------------------------------------------------
struct GSrc {
    const __half *Ah, *Bh, *Bl;
};

__device__ __forceinline__ void mma_core(
    GSrc s0, GSrc s1, int nchunk,
    const float* __restrict__ bias, float* __restrict__ C, int bm, int bn)
{
    extern __shared__ char sm[];
    const uint32_t sbase = smem_u32(sm);
    const int tid = threadIdx.x, wid = tid >> 5, l = tid & 31;
    const int wm = (wid & 3) * 32;   // warp row offset in CTA tile
    const int wn = (wid >> 2) * 64;  // warp col offset

    // stage copy: 3 tiles x 512 16B-chunks, 2 chunks per thread per tile
    auto issue = [&](int kc) {
        if (kc < nchunk) {
            const GSrc& s = (kc < 32) ? s0 : s1;
            const int kl = kc & 31;
            const uint32_t st = sbase + (kc % NSTAGE) * STAGEB;
            const __half* srcs[3] = {s.Ah, s.Bh, s.Bl};
#pragma unroll
            for (int t3 = 0; t3 < 3; ++t3) {
                const int rb = (t3 == 0) ? bm : bn;
                const uint32_t doff = st + t3 * TILEB;
                const __half* sp = srcs[t3];
#pragma unroll
                for (int j = 0; j < 2; ++j) {
                    int c = tid + j * 256;
                    int row = c >> 2, pos = c & 3;
                    uint32_t dst = doff + row * PITCHB + pos * 16;
                    const void* src = sp + (size_t)(rb + row) * DD + kl * 32 + pos * 8;
                    CPASYNC16(dst, src);
                }
            }
        }
        CPCOMMIT();
    };

    issue(0);
    issue(1);
    issue(2);

    float acc[2][8][4];
#pragma unroll
    for (int mi = 0; mi < 2; ++mi)
#pragma unroll
        for (int ni = 0; ni < 8; ++ni)
#pragma unroll
            for (int f = 0; f < 4; ++f) acc[mi][ni][f] = 0.0f;

    // ldmatrix per-lane addressing (m = l/8 selects the 8x8 matrix)
    const uint32_t m8 = l >> 3;
    const uint32_t laneArow = (m8 & 1) * 8 + (l & 7);
    const uint32_t laneAkb = (m8 >> 1) * 16;
    const uint32_t laneBrow = (m8 >> 1) * 8 + (l & 7);
    const uint32_t laneBkb = (m8 & 1) * 16;

    for (int kc = 0; kc < nchunk; ++kc) {
        CPWAIT2();
        __syncthreads();
        const uint32_t st = sbase + (kc % NSTAGE) * STAGEB;
#pragma unroll
        for (int ks = 0; ks < 2; ++ks) {
            const uint32_t kbyte = ks * 32;
            uint32_t ah[2][4];
#pragma unroll
            for (int mi = 0; mi < 2; ++mi) {
                uint32_t r = wm + mi * 16 + laneArow;
                ldsm4(ah[mi], st + 0 * TILEB + r * PITCHB + kbyte + laneAkb);
            }
            uint32_t bh[8][2], bl[8][2];
#pragma unroll
            for (int bi = 0; bi < 4; ++bi) {
                uint32_t r = wn + bi * 16 + laneBrow;
                uint32_t q[4];
                ldsm4(q, st + 1 * TILEB + r * PITCHB + kbyte + laneBkb);
                bh[bi * 2][0] = q[0]; bh[bi * 2][1] = q[1];
                bh[bi * 2 + 1][0] = q[2]; bh[bi * 2 + 1][1] = q[3];
                ldsm4(q, st + 2 * TILEB + r * PITCHB + kbyte + laneBkb);
                bl[bi * 2][0] = q[0]; bl[bi * 2][1] = q[1];
                bl[bi * 2 + 1][0] = q[2]; bl[bi * 2 + 1][1] = q[3];
            }
#pragma unroll
            for (int mi = 0; mi < 2; ++mi)
#pragma unroll
                for (int ni = 0; ni < 8; ++ni) {
                    mma16816(acc[mi][ni], ah[mi], bh[ni]);
                    mma16816(acc[mi][ni], ah[mi], bl[ni]);
                }
        }
        __syncthreads();
        issue(kc + NSTAGE);
    }

    // epilogue: acc frag f: rows l/4 (+8 for f>=2), cols (l%4)*2 + (f&1)
#pragma unroll
    for (int mi = 0; mi < 2; ++mi) {
        const int r0 = bm + wm + mi * 16 + (l >> 2);
#pragma unroll
        for (int ni = 0; ni < 8; ++ni) {
            const int c = bn + wn + ni * 8 + (l & 3) * 2;
            const float b0v = bias[c], b1v = bias[c + 1];
            float2 v0, v1;
            v0.x = acc[mi][ni][0] + b0v;
            v0.y = acc[mi][ni][1] + b1v;
            v1.x = acc[mi][ni][2] + b0v;
            v1.y = acc[mi][ni][3] + b1v;
            *(float2*)(C + (size_t)r0 * DD + c) = v0;
            *(float2*)(C + (size_t)(r0 + 8) * DD + c) = v1;
        }
    }
}

// batched QKV: z selects weight/bias/output; A = x (shared)
struct QkvPtrs {
    const __half* Bh[6];
    const __half* Bl[6];
    const float* bias[6];
    float* C[6];
};

__global__ __launch_bounds__(256) void mma_gemm_qkv(
    const __half* __restrict__ Ah, QkvPtrs p)
{
    int z = blockIdx.z;
    GSrc s{Ah, p.Bh[z], p.Bl[z]};
    mma_core(s, s, 32, p.bias[z], p.C[z], blockIdx.y * 128, blockIdx.x * 128);
}

__global__ __launch_bounds__(256) void mma_gemm_dual(
    const __half* A0h, const __half* B0h, const __half* B0l,
    const __half* A1h, const __half* B1h, const __half* B1l,
    const float* bias, float* C)
{
    GSrc s0{A0h, B0h, B0l};
    GSrc s1{A1h, B1h, B1l};
    mma_core(s0, s1, 64, bias, C, blockIdx.y * 128, blockIdx.x * 128);
}

// ---------------------------------------------------------------------------
// fp32 -> fp16 convert (hi only), vectorized
// ---------------------------------------------------------------------------
__global__ __launch_bounds__(256) void cvt_half(
    const float4* __restrict__ X, __half* __restrict__ H)
{
    size_t idx = (size_t)blockIdx.x * 256 + threadIdx.x;
    float4 v = X[idx];
    __half h[4];
    h[0] = __float2half(v.x);
    h[1] = __float2half(v.y);
    h[2] = __float2half(v.z);
    h[3] = __float2half(v.w);
    *(uint2*)(H + idx * 4) = *(uint2*)h;
}

// ---------------------------------------------------------------------------
// Weight transpose + split (z-batched): W[K=1024, N=1024] fp32 -> Th/Tl [N,K]
// ---------------------------------------------------------------------------
struct WtPtrs {
    const float* W[6];
    __half* Th[6];
    __half* Tl[6];
    int n;
};

__device__ __forceinline__ void wt_split_body(
    const float* __restrict__ W, __half* __restrict__ Th,
    __half* __restrict__ Tl)
{
    __shared__ float t[32][33];
    int tx = threadIdx.x, ty = threadIdx.y;
    int n0 = blockIdx.x * 32, k0 = blockIdx.y * 32;
#pragma unroll
    for (int j = 0; j < 4; ++j) {
        int k = k0 + ty + j * 8;
        t[ty + j * 8][tx] = W[(size_t)k * DD + n0 + tx];
    }
    __syncthreads();
#pragma unroll
    for (int j = 0; j < 4; ++j) {
        int n = n0 + ty + j * 8;
        int k = k0 + tx;
        float v = t[tx][ty + j * 8];
        __half h = __float2half(v);
        __half lo = __float2half(v - __half2float(h));
        Th[(size_t)n * DD + k] = h;
        Tl[(size_t)n * DD + k] = lo;
    }
}

__global__ void wt_split_batch(WtPtrs p)
{
    int z = blockIdx.z;
    wt_split_body(p.W[z], p.Th[z], p.Tl[z]);
}

// ---------------------------------------------------------------------------
// Scalar fp32 GEMM body (fixed 1024x1024x1024, no bias) + z=2 fold kernel
// ---------------------------------------------------------------------------
__device__ __forceinline__ void gemm_scalar_body(
    const float* __restrict__ A, const float* __restrict__ B,
    float* __restrict__ C)
{
    __shared__ float As[16][128];
    __shared__ float Bs[16][128];
    const int tid = threadIdx.x;
    const int bm = blockIdx.y * 128;
    const int bn = blockIdx.x * 128;
    const int tm = (tid >> 4) << 3;
    const int tn = (tid & 15) << 3;

    unsigned long long acc2[8][4];
#pragma unroll
    for (int i = 0; i < 8; ++i)
#pragma unroll
        for (int j = 0; j < 4; ++j) acc2[i][j] = 0ull;

    const int nk = DD >> 4;
    float4 aR[2], bR[2];
    auto loadTile = [&](int kt) {
        const int k0 = kt << 4;
#pragma unroll
        for (int j = 0; j < 2; ++j) {
            int i = tid + (j << 8);
            int ar = i >> 2, ac = (i & 3) << 2;
            aR[j] = *(const float4*)(A + (size_t)(bm + ar) * DD + k0 + ac);
            int br = i >> 5, bc = (i & 31) << 2;
            bR[j] = *(const float4*)(B + (size_t)(k0 + br) * DD + bn + bc);
        }
    };
    auto storeTile = [&]() {
#pragma unroll
        for (int j = 0; j < 2; ++j) {
            int i = tid + (j << 8);
            int ar = i >> 2, ac = (i & 3) << 2;
            As[ac + 0][ar] = aR[j].x;
            As[ac + 1][ar] = aR[j].y;
            As[ac + 2][ar] = aR[j].z;
            As[ac + 3][ar] = aR[j].w;
            int br = i >> 5, bc = (i & 31) << 2;
            *(float4*)&Bs[br][bc] = bR[j];
        }
    };
    loadTile(0);
    storeTile();
    __syncthreads();
    for (int kt = 0; kt < nk; ++kt) {
        if (kt + 1 < nk) loadTile(kt + 1);
#pragma unroll
        for (int k = 0; k < 16; ++k) {
            float4 a0 = *(const float4*)&As[k][tm];
            float4 a1 = *(const float4*)&As[k][tm + 4];
            float4 b0 = *(const float4*)&Bs[k][tn];
            float4 b1 = *(const float4*)&Bs[k][tn + 4];
            unsigned long long rbp[4] = {pk2(b0.x, b0.y), pk2(b0.z, b0.w),
                                         pk2(b1.x, b1.y), pk2(b1.z, b1.w)};
            float ra[8] = {a0.x, a0.y, a0.z, a0.w, a1.x, a1.y, a1.z, a1.w};
#pragma unroll
            for (int i = 0; i < 8; ++i) {
                unsigned long long aa = pk2(ra[i], ra[i]);
#pragma unroll
                for (int jp = 0; jp < 4; ++jp) fma2(acc2[i][jp], aa, rbp[jp]);
            }
        }
        __syncthreads();
        if (kt + 1 < nk) {
            storeTile();
            __syncthreads();
        }
    }
#pragma unroll
    for (int i = 0; i < 8; ++i) {
        float* crow = C + (size_t)(bm + tm + i) * DD + bn + tn;
#pragma unroll
        for (int jp = 0; jp < 4; ++jp) {
            float2 f = upk(acc2[i][jp]);
            *(float2*)(crow + 2 * jp) = f;
        }
    }
}

__global__ __launch_bounds__(256) void fold2_kernel(
    const float* __restrict__ sa_o_w, const float* __restrict__ ta_o_w,
    const float* __restrict__ fuse_w, float* __restrict__ W1,
    float* __restrict__ W2)
{
    if (blockIdx.z == 0)
        gemm_scalar_body(sa_o_w, fuse_w, W1);
    else
        gemm_scalar_body(ta_o_w, fuse_w + (size_t)DD * DD, W2);
}

// ---------------------------------------------------------------------------
// Merged attention: blocks [0,2048) temporal, [2048,4096) spatial.
// Both write fp16 outputs directly.
// ---------------------------------------------------------------------------
__device__ __forceinline__ void temporal_body(
    const float* __restrict__ Q, const float* __restrict__ Kp,
    const float* __restrict__ Vp, const int* __restrict__ mask,
    __half* __restrict__ O, int gid)
{
    __shared__ float Ks[64][64];
    __shared__ float Vs[64][64];
    __shared__ int Msk[64];

    int h = gid & 15;
    int clip = (gid >> 4) & 7;
    int b = gid >> 7;
    const size_t base = ((size_t)b * SS + clip) * DD + h * DK;
    const int RS = CLIPC * DD;

    int cq = threadIdx.x;
    unsigned long long qv[32];
    {
        const unsigned long long* qp =
            (const unsigned long long*)(Q + base + (size_t)cq * RS);
#pragma unroll
        for (int i = 0; i < 32; ++i) qv[i] = qp[i];
    }
    unsigned long long acc[32];
#pragma unroll
    for (int i = 0; i < 32; ++i) acc[i] = 0ull;
    float mmax = -1e30f, l = 0.f;

    const int lr = threadIdx.x >> 2;
    const int lc = (threadIdx.x & 3) << 4;

    for (int kt = 0; kt < 4; ++kt) {
        __syncthreads();
        {
            const float* krow = Kp + base + (size_t)(kt * 64 + lr) * RS;
            const float* vrow = Vp + base + (size_t)(kt * 64 + lr) * RS;
#pragma unroll
            for (int j = 0; j < 4; ++j) {
                *(float4*)&Ks[lr][lc + 4 * j] = *(const float4*)(krow + lc + 4 * j);
                *(float4*)&Vs[lr][lc + 4 * j] = *(const float4*)(vrow + lc + 4 * j);
            }
            if (threadIdx.x < 64)
                Msk[threadIdx.x] =
                    mask[(size_t)b * SS + (size_t)(kt * 64 + threadIdx.x) * CLIPC + clip];
        }
        __syncthreads();

        for (int kk = 0; kk < 64; ++kk) {
            if (Msk[kk] == 0) continue;
            const unsigned long long* kr = (const unsigned long long*)&Ks[kk][0];
            unsigned long long d2 = 0ull;
#pragma unroll
            for (int i = 0; i < 32; ++i) fma2(d2, qv[i], kr[i]);
            float2 dd = upk(d2);
            float s = (dd.x + dd.y) * 0.125f;
            if (s > mmax) {
                float corr = __expf(mmax - s);
                unsigned long long cc = pk2(corr, corr);
#pragma unroll
                for (int i = 0; i < 32; ++i) mul2(acc[i], cc);
                l *= corr;
                mmax = s;
            }
            float p = __expf(s - mmax);
            l += p;
            unsigned long long pp = pk2(p, p);
            const unsigned long long* vr = (const unsigned long long*)&Vs[kk][0];
#pragma unroll
            for (int i = 0; i < 32; ++i) fma2(acc[i], pp, vr[i]);
        }
    }
    float inv = 1.0f / l;
    __half2* op = (__half2*)(O + base + (size_t)cq * RS);
#pragma unroll
    for (int i = 0; i < 32; ++i) {
        float2 f = upk(acc[i]);
        op[i] = __floats2half2_rn(f.x * inv, f.y * inv);
    }
}

__device__ __forceinline__ void spatial_body(
    const float* __restrict__ Q, const float* __restrict__ Kp,
    const float* __restrict__ Vp, const int* __restrict__ mask,
    __half* __restrict__ O, int blk)
{
    int unit = blk * 2 + (threadIdx.x >> 7);
    int t = threadIdx.x & 127;
    int h = t >> 3, qi = t & 7;
    int b = unit >> 8, nc = unit & 255;
    size_t rowBase = (size_t)b * SS + (size_t)nc * CLIPC;

    unsigned long long qv[32];
    {
        const unsigned long long* qp =
            (const unsigned long long*)(Q + (rowBase + qi) * DD + h * DK);
#pragma unroll
        for (int i = 0; i < 32; ++i) qv[i] = qp[i];
    }
    const float* kbase = Kp + rowBase * DD + h * DK;
    float sc[8];
    float mx = -1e30f;
#pragma unroll
    for (int kk = 0; kk < 8; ++kk) {
        const unsigned long long* kr =
            (const unsigned long long*)(kbase + (size_t)kk * DD);
        unsigned long long d2 = 0ull;
#pragma unroll
        for (int i = 0; i < 32; ++i) fma2(d2, qv[i], kr[i]);
        float2 dd = upk(d2);
        float s = (dd.x + dd.y) * 0.125f;
        sc[kk] = (mask[rowBase + kk] != 0) ? s : -1e30f;
        mx = fmaxf(mx, sc[kk]);
    }
    float p[8], sum = 0.f;
#pragma unroll
    for (int kk = 0; kk < 8; ++kk) {
        p[kk] = __expf(sc[kk] - mx);
        sum += p[kk];
    }
    float inv = 1.0f / sum;
    unsigned long long acc[32];
#pragma unroll
    for (int i = 0; i < 32; ++i) acc[i] = 0ull;
    const float* vbase = Vp + rowBase * DD + h * DK;
#pragma unroll
    for (int kk = 0; kk < 8; ++kk) {
        unsigned long long pp = pk2(p[kk], p[kk]);
        const unsigned long long* vr =
            (const unsigned long long*)(vbase + (size_t)kk * DD);
#pragma unroll
        for (int i = 0; i < 32; ++i) fma2(acc[i], pp, vr[i]);
    }
    __half2* op = (__half2*)(O + (rowBase + qi) * DD + h * DK);
#pragma unroll
    for (int i = 0; i < 32; ++i) {
        float2 f = upk(acc[i]);
        op[i] = __floats2half2_rn(f.x * inv, f.y * inv);
    }
}

__global__ __launch_bounds__(256) void attn_merged(
    const float* __restrict__ qs, const float* __restrict__ ks,
    const float* __restrict__ vs, const float* __restrict__ qt,
    const float* __restrict__ kt, const float* __restrict__ vt,
    const int* __restrict__ mask, __half* __restrict__ csh,
    __half* __restrict__ cth)
{
    int blk = blockIdx.x;
    if (blk < BB * CLIPC * HH) {
        temporal_body(qt, kt, vt, mask, cth, blk);  // long blocks first
    } else {
        spatial_body(qs, ks, vs, mask, csh, blk - BB * CLIPC * HH);
    }
}

// ---------------------------------------------------------------------------
// bias combine, parallel 2-stage
// ---------------------------------------------------------------------------
__global__ void bias_partial(const float* __restrict__ sab,
                             const float* __restrict__ tab,
                             const float* __restrict__ fw,
                             float* __restrict__ part)
{
    int n = blockIdx.x * 256 + threadIdx.x;
    int j = blockIdx.y;
    int k0 = j * 64;
    float s = 0.f;
#pragma unroll 8
    for (int k = k0; k < k0 + 64; ++k) {
        float coef = (k < DD) ? sab[k] : tab[k - DD];
        s += coef * fw[(size_t)k * DD + n];
    }
    part[(size_t)j * DD + n] = s;
}

__global__ void bias_reduce(const float* __restrict__ part,
                            const float* __restrict__ fb,
                            float* __restrict__ bc)
{
    int n = blockIdx.x * 256 + threadIdx.x;
    float s = fb[n];
#pragma unroll
    for (int j = 0; j < 32; ++j) s += part[(size_t)j * DD + n];
    bc[n] = s;
}

// ---------------------------------------------------------------------------
// Launch sequence (ordered so launch index 5 = mma_gemm_qkv for ncu -s 5)
// ---------------------------------------------------------------------------
extern "C" void kernel_launch(void* const* d_in, const int* in_sizes, int n_in,
                              void* d_out, int out_size)
{
    const float* x       = (const float*)d_in[0];
    const int*   mask    = (const int*)d_in[1];
    const float* sa_q_w  = (const float*)d_in[2];
    const float* sa_q_b  = (const float*)d_in[3];
    const float* sa_k_w  = (const float*)d_in[4];
    const float* sa_k_b  = (const float*)d_in[5];
    const float* sa_v_w  = (const float*)d_in[6];
    const float* sa_v_b  = (const float*)d_in[7];
    const float* sa_o_w  = (const float*)d_in[8];
    const float* sa_o_b  = (const float*)d_in[9];
    const float* ta_q_w  = (const float*)d_in[10];
    const float* ta_q_b  = (const float*)d_in[11];
    const float* ta_k_w  = (const float*)d_in[12];
    const float* ta_k_b  = (const float*)d_in[13];
    const float* ta_v_w  = (const float*)d_in[14];
    const float* ta_v_b  = (const float*)d_in[15];
    const float* ta_o_w  = (const float*)d_in[16];
    const float* ta_o_b  = (const float*)d_in[17];
    const float* fuse_w  = (const float*)d_in[18];
    const float* fuse_b  = (const float*)d_in[19];
    float* out = (float*)d_out;

    float *qs, *ks, *vs, *qt, *kt, *vt, *W1, *W2, *bc, *bcp;
    cudaGetSymbolAddress((void**)&qs, g_qs);
    cudaGetSymbolAddress((void**)&ks, g_ks);
    cudaGetSymbolAddress((void**)&vs, g_vs);
    cudaGetSymbolAddress((void**)&qt, g_qt);
    cudaGetSymbolAddress((void**)&kt, g_kt);
    cudaGetSymbolAddress((void**)&vt, g_vt);
    cudaGetSymbolAddress((void**)&W1, g_W1);
    cudaGetSymbolAddress((void**)&W2, g_W2);
    cudaGetSymbolAddress((void**)&bc, g_bc);
    cudaGetSymbolAddress((void**)&bcp, g_bcp);

    __half *xh, *csh, *cth, *wth, *wtl;
    cudaGetSymbolAddress((void**)&xh, g_xh);
    cudaGetSymbolAddress((void**)&csh, g_csh);
    cudaGetSymbolAddress((void**)&cth, g_cth);
    cudaGetSymbolAddress((void**)&wth, g_wth);
    cudaGetSymbolAddress((void**)&wtl, g_wtl);
    const size_t WSZ = (size_t)DD * DD;

    cudaFuncSetAttribute(mma_gemm_qkv, cudaFuncAttributeMaxDynamicSharedMemorySize,
                         SMEM_DYN);
    cudaFuncSetAttribute(mma_gemm_dual, cudaFuncAttributeMaxDynamicSharedMemorySize,
                         SMEM_DYN);

    const int nBlkCvt = MROWS * DD / 4 / 256;  // 32768
    dim3 bT(32, 8);

    // 0) convert x to fp16
    cvt_half<<<nBlkCvt, 256>>>((const float4*)x, xh);

    // 1) transpose + split the six QKV weights (z-batched)
    {
        WtPtrs wp;
        const float* ws[6] = {sa_q_w, sa_k_w, sa_v_w, ta_q_w, ta_k_w, ta_v_w};
        for (int i = 0; i < 6; ++i) {
            wp.W[i] = ws[i];
            wp.Th[i] = wth + i * WSZ;
            wp.Tl[i] = wtl + i * WSZ;
        }
        wp.n = 6;
        wt_split_batch<<<dim3(32, 32, 6), bT>>>(wp);
    }

    // 2) fold o-proj into fuse: W1 = sa_o_w@fuse_top, W2 = ta_o_w@fuse_bot (z=2)
    fold2_kernel<<<dim3(8, 8, 2), 256>>>(sa_o_w, ta_o_w, fuse_w, W1, W2);

    // 3,4) combined bias
    bias_partial<<<dim3(4, 32), 256>>>(sa_o_b, ta_o_b, fuse_w, bcp);
    bias_reduce<<<4, 256>>>(bcp, fuse_b, bc);

    // 5) six QKV projections on tensor cores  ← ncu -s 5 profiles this
    QkvPtrs qp;
    float* outs[6] = {qs, ks, vs, qt, kt, vt};
    const float* biases[6] = {sa_q_b, sa_k_b, sa_v_b, ta_q_b, ta_k_b, ta_v_b};
    for (int i = 0; i < 6; ++i) {
        qp.Bh[i] = wth + i * WSZ;
        qp.Bl[i] = wtl + i * WSZ;
        qp.bias[i] = biases[i];
        qp.C[i] = outs[i];
    }
    mma_gemm_qkv<<<dim3(DD / 128, MROWS / 128, 6), 256, SMEM_DYN>>>(xh, qp);

    // 6) transpose + split folded W1/W2 (z-batched)
    {
        WtPtrs wp;
        wp.W[0] = W1; wp.Th[0] = wth + 6 * WSZ; wp.Tl[0] = wtl + 6 * WSZ;
        wp.W[1] = W2; wp.Th[1] = wth + 7 * WSZ; wp.Tl[1] = wtl + 7 * WSZ;
        wp.n = 2;
        wt_split_batch<<<dim3(32, 32, 2), bT>>>(wp);
    }

    // 7) merged attention (temporal blocks first, spatial backfills)
    attn_merged<<<BB * CLIPC * HH + BB * NCC / 2, 256>>>(
        qs, ks, vs, qt, kt, vt, mask, csh, cth);

    // 8) fused output: out = cs@W1t + ct@W2t + bc (single dual-K tensor GEMM)
    mma_gemm_dual<<<dim3(DD / 128, MROWS / 128), 256, SMEM_DYN>>>(
        csh, wth + 6 * WSZ, wtl + 6 * WSZ,
        cth, wth + 7 * WSZ, wtl + 7 * WSZ,
        bc, out);
}